// round 2
// baseline (speedup 1.0000x reference)
#include <cuda_runtime.h>
#include <cstdint>

#define N_NODES 16384
#define N_EDGES 131072
#define F_IN 6
#define S_DIM 4
#define G_NUM 256
#define HH 30
#define C1 32
#define C2 64
#define C3 32

typedef unsigned long long ull;

// ---------------- scratch (no cudaMalloc allowed) ----------------
__device__ float g_B1[N_NODES * C1];   // ECC1 agg -> x1
__device__ float g_B2[N_NODES * C2];   // ECC2 agg -> x2
__device__ float g_XW[N_NODES * C3];   // x2 @ gcn_W
__device__ float g_B3[N_NODES * C3];   // GCN agg -> x3

// packed f32x2 FMA (Blackwell)
__device__ __forceinline__ void ffma2(ull &acc, ull a, ull b) {
    asm("fma.rn.f32x2 %0, %1, %2, %0;" : "+l"(acc) : "l"(a), "l"(b));
}

// ---------------- ECC edge kernel: fused MLP + P@B GEMM + scatter ----------------
// msg[e,c] = sum_{h,f} h2[e,h]*xs[e,f]*wk[h, f*C+c] + sum_f xs[e,f]*bk[f*C+c]
//          = (P @ B)[e,c],  P[e, h*F+f] = h2*xs,  B = wk viewed [H*F, C] (+ F bias rows)
template <int F, int C>
struct EccSmem {
    static constexpr int TM = 128;
    static constexpr int KC = 32;
    float w0[S_DIM * HH];
    float b0v[HH];
    float w1[HH * HH];
    float b1v[HH];
    float ef[TM * S_DIM];
    int   srcs[TM];
    int   tgts[TM];
    float h1[TM * HH];
    float h2[TM * HH];
    float xs[TM * F];
    ull   A[TM * KC];        // duplicated {a,a} per element
    ull   B[KC * (C / 2)];   // B rows as float2 pairs
};

template <int F, int C>
__global__ __launch_bounds__(256) void ecc_edge_kernel(
    const float* __restrict__ xin, const float* __restrict__ efeat,
    const int* __restrict__ src, const int* __restrict__ tgt,
    const float* __restrict__ w0, const float* __restrict__ b0,
    const float* __restrict__ w1, const float* __restrict__ b1,
    const float* __restrict__ wk, const float* __restrict__ bk,
    float* __restrict__ agg)
{
    constexpr int TM = 128, KC = 32, NT = 256;
    constexpr int K_MAIN = HH * F;
    constexpr int K_TOT  = K_MAIN + F;
    constexpr int NSLAB  = (K_TOT + KC - 1) / KC;
    constexpr int NCG    = C / 4;            // 4 output cols per thread
    constexpr int RM     = TM / (NT / NCG);  // rows per thread (ECC1:4, ECC2:8)

    extern __shared__ __align__(16) char smraw[];
    EccSmem<F, C>& S = *reinterpret_cast<EccSmem<F, C>*>(smraw);

    const int tid = threadIdx.x;
    const int i0  = blockIdx.x * TM;

    // --- stage 0: weights + edge tile + indices ---
    for (int j = tid; j < S_DIM * HH; j += NT) S.w0[j] = w0[j];
    for (int j = tid; j < HH; j += NT) { S.b0v[j] = b0[j]; S.b1v[j] = b1[j]; }
    for (int j = tid; j < HH * HH; j += NT) S.w1[j] = w1[j];
    for (int j = tid; j < TM * S_DIM; j += NT) S.ef[j] = efeat[(size_t)i0 * S_DIM + j];
    for (int j = tid; j < TM; j += NT) { S.srcs[j] = src[i0 + j]; S.tgts[j] = tgt[i0 + j]; }
    __syncthreads();

    // --- gather x[src] tile ---
    for (int j = tid; j < TM * F; j += NT) {
        int i = j / F, f = j - i * F;
        S.xs[j] = xin[(size_t)S.srcs[i] * F + f];
    }
    // --- edge MLP: h1 = relu(e@w0+b0), h2 = relu(h1@w1+b1) ---
    for (int j = tid; j < TM * HH; j += NT) {
        int i = j / HH, jj = j - i * HH;
        float a = S.b0v[jj];
        #pragma unroll
        for (int s = 0; s < S_DIM; s++) a += S.ef[i * S_DIM + s] * S.w0[s * HH + jj];
        S.h1[j] = fmaxf(a, 0.f);
    }
    __syncthreads();
    for (int j = tid; j < TM * HH; j += NT) {
        int i = j / HH, jj = j - i * HH;
        float a = S.b1v[jj];
        #pragma unroll
        for (int h = 0; h < HH; h++) a += S.h1[i * HH + h] * S.w1[h * HH + jj];
        S.h2[j] = fmaxf(a, 0.f);
    }

    // --- stage 1: tiled GEMM MSG[TM,C] = P @ B with f32x2 packing ---
    const int cg   = tid % NCG;            // column group (4 cols)
    const int row0 = (tid / NCG) * RM;

    ull acc[RM][2];
    #pragma unroll
    for (int r = 0; r < RM; r++) { acc[r][0] = 0ull; acc[r][1] = 0ull; }

    for (int slab = 0; slab < NSLAB; slab++) {
        const int k0 = slab * KC;
        __syncthreads();  // protect A/B from previous iteration readers

        // build A slab: A[i,kk] = {a,a}
        for (int j = tid; j < TM * KC; j += NT) {
            int i = j / KC, kk = j - i * KC;
            int k = k0 + kk;
            float a;
            if (k < K_MAIN)       a = S.h2[i * HH + k / F] * S.xs[i * F + k % F];
            else if (k < K_TOT)   a = S.xs[i * F + (k - K_MAIN)];
            else                  a = 0.f;
            unsigned u = __float_as_uint(a);
            S.A[j] = ((ull)u << 32) | u;
        }
        // load B slab (wk is already the right layout; bias rows from bk)
        for (int j = tid; j < KC * (C / 2); j += NT) {
            int kk = j / (C / 2), cp = j - kk * (C / 2);
            int k = k0 + kk;
            float2 bv;
            if (k < K_MAIN)      bv = reinterpret_cast<const float2*>(wk)[(size_t)k * (C / 2) + cp];
            else if (k < K_TOT)  bv = reinterpret_cast<const float2*>(bk)[(size_t)(k - K_MAIN) * (C / 2) + cp];
            else                 bv = make_float2(0.f, 0.f);
            S.B[j] = ((ull)__float_as_uint(bv.y) << 32) | (ull)__float_as_uint(bv.x);
        }
        __syncthreads();

        #pragma unroll 4
        for (int kk = 0; kk < KC; kk++) {
            ull bv0 = S.B[kk * (C / 2) + 2 * cg];
            ull bv1 = S.B[kk * (C / 2) + 2 * cg + 1];
            #pragma unroll
            for (int r = 0; r < RM; r++) {
                ull av = S.A[(row0 + r) * KC + kk];
                ffma2(acc[r][0], av, bv0);
                ffma2(acc[r][1], av, bv1);
            }
        }
    }

    // --- stage 2: scatter-add to agg[tgt] ---
    #pragma unroll
    for (int r = 0; r < RM; r++) {
        int i = row0 + r;
        float* dst = agg + (size_t)S.tgts[i] * C + 4 * cg;
        float2 v0 = *reinterpret_cast<float2*>(&acc[r][0]);
        float2 v1 = *reinterpret_cast<float2*>(&acc[r][1]);
        atomicAdd(dst + 0, v0.x);
        atomicAdd(dst + 1, v0.y);
        atomicAdd(dst + 2, v1.x);
        atomicAdd(dst + 3, v1.y);
    }
}

// ---------------- node-side small GEMM: out[n,c] = bias[c] + x[n,:]@root[:,c] ----------------
template <int F, int C, bool HAS_BIAS>
__global__ void base_kernel(const float* __restrict__ x, const float* __restrict__ root,
                            const float* __restrict__ bias, float* __restrict__ out)
{
    int gid = blockIdx.x * blockDim.x + threadIdx.x;
    if (gid >= N_NODES * C) return;
    int n = gid / C, c = gid - n * C;
    float a = HAS_BIAS ? __ldg(bias + c) : 0.f;
    #pragma unroll
    for (int f = 0; f < F; f++) a += __ldg(x + (size_t)n * F + f) * __ldg(root + f * C + c);
    out[gid] = a;
}

__global__ void relu_kernel(float* __restrict__ buf, int n)
{
    int i = blockIdx.x * blockDim.x + threadIdx.x;
    if (i < n) buf[i] = fmaxf(buf[i], 0.f);
}

__global__ void zero_kernel(float* __restrict__ buf, int n)
{
    int i = blockIdx.x * blockDim.x + threadIdx.x;
    if (i < n) buf[i] = 0.f;
}

// GCN weighted SpMM: b3[tgt,c] += w * xw[src,c]   (warp = one edge, lane = channel)
__global__ void gcn_edge_kernel(const float* __restrict__ xw,
                                const int* __restrict__ gs, const int* __restrict__ gt,
                                const float* __restrict__ gw, float* __restrict__ b3)
{
    int gid = blockIdx.x * blockDim.x + threadIdx.x;
    int m = gid >> 5, c = gid & 31;
    if (m >= N_EDGES + N_NODES) return;
    float v = __ldg(gw + m) * __ldg(xw + (size_t)__ldg(gs + m) * C3 + c);
    atomicAdd(&b3[(size_t)__ldg(gt + m) * C3 + c], v);
}

// x3 = relu(b3 + gcn_b); out[seg[n],c] += x3[n,c]
__global__ void pool_kernel(const float* __restrict__ b3, const float* __restrict__ gb,
                            const int* __restrict__ seg, float* __restrict__ out)
{
    int gid = blockIdx.x * blockDim.x + threadIdx.x;
    int n = gid >> 5, c = gid & 31;
    if (n >= N_NODES) return;
    float v = fmaxf(b3[gid] + __ldg(gb + c), 0.f);
    atomicAdd(&out[(size_t)__ldg(seg + n) * C3 + c], v);
}

// ---------------- launch ----------------
extern "C" void kernel_launch(void* const* d_in, const int* in_sizes, int n_in,
                              void* d_out, int out_size)
{
    (void)in_sizes; (void)n_in; (void)out_size;
    const float* x     = (const float*)d_in[0];
    const float* e     = (const float*)d_in[1];
    const int*   src   = (const int*)d_in[2];
    const int*   tgt   = (const int*)d_in[3];
    const int*   seg   = (const int*)d_in[4];
    const int*   gsrc  = (const int*)d_in[5];
    const int*   gtgt  = (const int*)d_in[6];
    const float* gw    = (const float*)d_in[7];
    const float* e1_w0 = (const float*)d_in[8];
    const float* e1_b0 = (const float*)d_in[9];
    const float* e1_w1 = (const float*)d_in[10];
    const float* e1_b1 = (const float*)d_in[11];
    const float* e1_wk = (const float*)d_in[12];
    const float* e1_bk = (const float*)d_in[13];
    const float* e1_root = (const float*)d_in[14];
    const float* e1_bias = (const float*)d_in[15];
    const float* e2_w0 = (const float*)d_in[16];
    const float* e2_b0 = (const float*)d_in[17];
    const float* e2_w1 = (const float*)d_in[18];
    const float* e2_b1 = (const float*)d_in[19];
    const float* e2_wk = (const float*)d_in[20];
    const float* e2_bk = (const float*)d_in[21];
    const float* e2_root = (const float*)d_in[22];
    const float* e2_bias = (const float*)d_in[23];
    const float* gcn_W = (const float*)d_in[24];
    const float* gcn_b = (const float*)d_in[25];
    float* out = (float*)d_out;

    float *B1, *B2, *XW, *B3;
    cudaGetSymbolAddress((void**)&B1, g_B1);
    cudaGetSymbolAddress((void**)&B2, g_B2);
    cudaGetSymbolAddress((void**)&XW, g_XW);
    cudaGetSymbolAddress((void**)&B3, g_B3);

    const int smem1 = (int)sizeof(EccSmem<F_IN, C1>);
    const int smem2 = (int)sizeof(EccSmem<C1, C2>);
    cudaFuncSetAttribute((const void*)ecc_edge_kernel<F_IN, C1>,
                         cudaFuncAttributeMaxDynamicSharedMemorySize, smem1);
    cudaFuncSetAttribute((const void*)ecc_edge_kernel<C1, C2>,
                         cudaFuncAttributeMaxDynamicSharedMemorySize, smem2);

    // ECC layer 1: agg1 = x@root1+b; += messages; relu
    base_kernel<F_IN, C1, true><<<(N_NODES * C1 + 255) / 256, 256>>>(x, e1_root, e1_bias, B1);
    ecc_edge_kernel<F_IN, C1><<<N_EDGES / 128, 256, smem1>>>(
        x, e, src, tgt, e1_w0, e1_b0, e1_w1, e1_b1, e1_wk, e1_bk, B1);
    relu_kernel<<<(N_NODES * C1 + 255) / 256, 256>>>(B1, N_NODES * C1);

    // ECC layer 2
    base_kernel<C1, C2, true><<<(N_NODES * C2 + 255) / 256, 256>>>(B1, e2_root, e2_bias, B2);
    ecc_edge_kernel<C1, C2><<<N_EDGES / 128, 256, smem2>>>(
        B1, e, src, tgt, e2_w0, e2_b0, e2_w1, e2_b1, e2_wk, e2_bk, B2);
    relu_kernel<<<(N_NODES * C2 + 255) / 256, 256>>>(B2, N_NODES * C2);

    // GCN: xw = x2 @ W ; b3 = scatter(gcn_w * xw[gcn_src] -> gcn_tgt)
    base_kernel<C2, C3, false><<<(N_NODES * C3 + 255) / 256, 256>>>(B2, gcn_W, nullptr, XW);
    zero_kernel<<<(N_NODES * C3 + 255) / 256, 256>>>(B3, N_NODES * C3);
    gcn_edge_kernel<<<((N_EDGES + N_NODES) * 32 + 255) / 256, 256>>>(XW, gsrc, gtgt, gw, B3);

    // relu(+bias) and global sum pool
    zero_kernel<<<(G_NUM * C3 + 255) / 256, 256>>>(out, G_NUM * C3);
    pool_kernel<<<(N_NODES * C3 + 255) / 256, 256>>>(B3, gcn_b, seg, out);
}